// round 1
// baseline (speedup 1.0000x reference)
#include <cuda_runtime.h>
#include <math.h>

#define NROWS 8192
#define D     128
#define TM    128
#define TN    128
#define KC    32

// Scratch (allocation-free rule: __device__ globals)
__device__ float g_h1n[NROWS * D];
__device__ float g_h2n[NROWS * D];
__device__ float g_R[4 * NROWS];   // [R11 | R12row | R12col | R22]
__device__ float g_diag[NROWS];

// ---------------------------------------------------------------------------
// Zero the accumulators (must run every launch: atomics accumulate)
// ---------------------------------------------------------------------------
__global__ void zero_kernel() {
    int i = blockIdx.x * blockDim.x + threadIdx.x;
    if (i < 4 * NROWS) g_R[i] = 0.0f;
}

// ---------------------------------------------------------------------------
// Row-normalize h1,h2 (one warp per row pair) + diag12 = <h1n_i, h2n_i>
// ---------------------------------------------------------------------------
__global__ void norm_kernel(const float* __restrict__ h1,
                            const float* __restrict__ h2) {
    int gt   = blockIdx.x * blockDim.x + threadIdx.x;
    int w    = gt >> 5;
    int lane = gt & 31;
    if (w >= NROWS) return;

    float4 v1 = ((const float4*)(h1 + (size_t)w * D))[lane];
    float4 v2 = ((const float4*)(h2 + (size_t)w * D))[lane];

    float ss1 = v1.x*v1.x + v1.y*v1.y + v1.z*v1.z + v1.w*v1.w;
    float ss2 = v2.x*v2.x + v2.y*v2.y + v2.z*v2.z + v2.w*v2.w;
    float dt  = v1.x*v2.x + v1.y*v2.y + v1.z*v2.z + v1.w*v2.w;

    #pragma unroll
    for (int m = 16; m > 0; m >>= 1) {
        ss1 += __shfl_xor_sync(0xffffffffu, ss1, m);
        ss2 += __shfl_xor_sync(0xffffffffu, ss2, m);
        dt  += __shfl_xor_sync(0xffffffffu, dt,  m);
    }

    float inv1 = 1.0f / fmaxf(sqrtf(ss1), 1e-12f);
    float inv2 = 1.0f / fmaxf(sqrtf(ss2), 1e-12f);

    float4 o1 = make_float4(v1.x*inv1, v1.y*inv1, v1.z*inv1, v1.w*inv1);
    float4 o2 = make_float4(v2.x*inv2, v2.y*inv2, v2.z*inv2, v2.w*inv2);
    ((float4*)(g_h1n + (size_t)w * D))[lane] = o1;
    ((float4*)(g_h2n + (size_t)w * D))[lane] = o2;

    if (lane == 0) g_diag[w] = dt * inv1 * inv2;
}

// ---------------------------------------------------------------------------
// Fused tile GEMM + exp(5*s) + row/col sum scatter.
// mode 0: S11 (sym, A=B=h1n, sums -> R11)
// mode 1: S22 (sym, A=B=h2n, sums -> R22)
// mode 2: S12 (A=h1n, B=h2n, rowsum -> R12row, colsum -> R12col)
// Symmetric modes compute only J>=I tiles; off-diagonal tiles scatter their
// column sums to the mirrored rows.
// ---------------------------------------------------------------------------
__global__ void __launch_bounds__(256, 2) gemm_exp_kernel(int mode) {
    const float* A; const float* B; float* Rrow; float* Rcol; bool sym;
    if (mode == 0)      { A = g_h1n; B = g_h1n; Rrow = g_R;             Rcol = Rrow; sym = true;  }
    else if (mode == 1) { A = g_h2n; B = g_h2n; Rrow = g_R + 3*NROWS;   Rcol = Rrow; sym = true;  }
    else                { A = g_h1n; B = g_h2n; Rrow = g_R + NROWS;     Rcol = g_R + 2*NROWS; sym = false; }

    int I = blockIdx.y;
    int J = blockIdx.x;
    if (sym && J < I) return;

    __shared__ float As[KC][TM + 4];     // [k][m], stride 132 (16B-aligned rows)
    __shared__ float Bs[KC][TN + 4];
    __shared__ float red[16][TN + 4];    // col-sum staging

    int t  = threadIdx.x;
    int tx = t & 15;       // N direction (8 cols each)
    int ty = t >> 4;       // M direction (8 rows each)

    float acc[8][8];
    #pragma unroll
    for (int r = 0; r < 8; r++)
        #pragma unroll
        for (int c = 0; c < 8; c++) acc[r][c] = 0.0f;

    const float* Ab = A + (size_t)I * TM * D;
    const float* Bb = B + (size_t)J * TN * D;

    int lrow = t >> 3;          // 0..31
    int lk   = (t & 7) << 2;    // 0,4,...,28

    for (int kc = 0; kc < D; kc += KC) {
        // Coalesced global float4 loads, transposed store into [k][m] smem
        #pragma unroll
        for (int i = 0; i < 4; i++) {
            int row = lrow + i * 32;
            float4 va = *(const float4*)(Ab + (size_t)row * D + kc + lk);
            As[lk + 0][row] = va.x; As[lk + 1][row] = va.y;
            As[lk + 2][row] = va.z; As[lk + 3][row] = va.w;
            float4 vb = *(const float4*)(Bb + (size_t)row * D + kc + lk);
            Bs[lk + 0][row] = vb.x; Bs[lk + 1][row] = vb.y;
            Bs[lk + 2][row] = vb.z; Bs[lk + 3][row] = vb.w;
        }
        __syncthreads();

        #pragma unroll 8
        for (int k = 0; k < KC; k++) {
            float a[8], b[8];
            *(float4*)(a)     = *(const float4*)(&As[k][ty * 8]);
            *(float4*)(a + 4) = *(const float4*)(&As[k][ty * 8 + 4]);
            *(float4*)(b)     = *(const float4*)(&Bs[k][tx * 8]);
            *(float4*)(b + 4) = *(const float4*)(&Bs[k][tx * 8 + 4]);
            #pragma unroll
            for (int r = 0; r < 8; r++)
                #pragma unroll
                for (int c = 0; c < 8; c++)
                    acc[r][c] += a[r] * b[c];
        }
        __syncthreads();
    }

    // Epilogue: exp(5*s), accumulate row partials and column partials
    float rp[8], cp[8];
    #pragma unroll
    for (int r = 0; r < 8; r++) rp[r] = 0.0f;
    #pragma unroll
    for (int c = 0; c < 8; c++) cp[c] = 0.0f;

    #pragma unroll
    for (int r = 0; r < 8; r++)
        #pragma unroll
        for (int c = 0; c < 8; c++) {
            float e = __expf(5.0f * acc[r][c]);
            rp[r] += e;
            cp[c] += e;
        }

    // Row sums: reduce across tx (lanes 0-15 of each half-warp)
    #pragma unroll
    for (int r = 0; r < 8; r++) {
        #pragma unroll
        for (int m = 1; m < 16; m <<= 1)
            rp[r] += __shfl_xor_sync(0xffffffffu, rp[r], m);
    }
    if (tx == 0) {
        #pragma unroll
        for (int r = 0; r < 8; r++)
            atomicAdd(&Rrow[I * TM + ty * 8 + r], rp[r]);
    }

    // Column sums: needed for cross tiles and off-diagonal symmetric tiles
    bool needcol = (!sym) || (J > I);
    if (needcol) {
        #pragma unroll
        for (int c = 0; c < 8; c++) red[ty][tx * 8 + c] = cp[c];
        __syncthreads();
        if (t < TN) {
            float s = 0.0f;
            #pragma unroll
            for (int y = 0; y < 16; y++) s += red[y][t];
            atomicAdd(&Rcol[J * TN + t], s);
        }
    }
}

// ---------------------------------------------------------------------------
// Final scalar: mean over i of 0.5*(log(neg1)+log(neg2)) - 5*diag12
// neg1 = R11 + R12row - e^5 ; neg2 = R22 + R12col - e^5
// ---------------------------------------------------------------------------
__global__ void final_kernel(float* out) {
    __shared__ float sm[256];
    int t = threadIdx.x;
    const float E5 = 148.4131591f;   // exp(5) = exp(1/tau), tau = 0.2

    float s = 0.0f;
    for (int i = t; i < NROWS; i += 256) {
        float n1 = g_R[i]             + g_R[NROWS + i]     - E5;
        float n2 = g_R[3 * NROWS + i] + g_R[2 * NROWS + i] - E5;
        s += 0.5f * (logf(n1) + logf(n2)) - 5.0f * g_diag[i];
    }
    sm[t] = s;
    __syncthreads();
    #pragma unroll
    for (int o = 128; o > 0; o >>= 1) {
        if (t < o) sm[t] += sm[t + o];
        __syncthreads();
    }
    if (t == 0) out[0] = sm[0] * (1.0f / NROWS);
}

// ---------------------------------------------------------------------------
extern "C" void kernel_launch(void* const* d_in, const int* in_sizes, int n_in,
                              void* d_out, int out_size) {
    const float* h1 = (const float*)d_in[0];
    const float* h2 = (const float*)d_in[1];
    float* out = (float*)d_out;

    zero_kernel<<<(4 * NROWS + 255) / 256, 256>>>();
    norm_kernel<<<(NROWS * 32) / 256, 256>>>(h1, h2);

    dim3 grid(NROWS / TN, NROWS / TM);   // 64 x 64
    gemm_exp_kernel<<<grid, 256>>>(0);   // S11 (upper triangle)
    gemm_exp_kernel<<<grid, 256>>>(1);   // S22 (upper triangle)
    gemm_exp_kernel<<<grid, 256>>>(2);   // S12 (full, row+col sums)

    final_kernel<<<1, 256>>>(out);
}

// round 3
// speedup vs baseline: 5.6807x; 5.6807x over previous
#include <cuda_runtime.h>
#include <cuda_bf16.h>
#include <math.h>
#include <stdint.h>

#define NROWS 8192
#define DDIM  128
#define TM    128
#define TN    128

// Scratch (__device__ globals: allocation-free rule)
__device__ __nv_bfloat16 g_h1b[NROWS * DDIM];
__device__ __nv_bfloat16 g_h2b[NROWS * DDIM];
__device__ float g_R[4 * NROWS];   // [R11 | R12row | R12col | R22]
__device__ float g_diag[NROWS];

// ---------------------------------------------------------------------------
// MMA / ldmatrix helpers (family-portable: compile for base sm_103)
// ---------------------------------------------------------------------------
__device__ __forceinline__ uint32_t smem_u32(const void* p) {
    uint32_t a;
    asm("{ .reg .u64 t; cvta.to.shared.u64 t, %1; cvt.u32.u64 %0, t; }"
        : "=r"(a) : "l"(p));
    return a;
}

__device__ __forceinline__ void ldsm_x4(uint32_t& r0, uint32_t& r1,
                                        uint32_t& r2, uint32_t& r3, uint32_t addr) {
    asm volatile("ldmatrix.sync.aligned.m8n8.x4.shared.b16 {%0,%1,%2,%3}, [%4];"
                 : "=r"(r0), "=r"(r1), "=r"(r2), "=r"(r3) : "r"(addr));
}

__device__ __forceinline__ void mma16816(float* d, const uint32_t* a, const uint32_t* b) {
    asm volatile(
        "mma.sync.aligned.m16n8k16.row.col.f32.bf16.bf16.f32 "
        "{%0,%1,%2,%3}, {%4,%5,%6,%7}, {%8,%9}, {%0,%1,%2,%3};"
        : "+f"(d[0]), "+f"(d[1]), "+f"(d[2]), "+f"(d[3])
        : "r"(a[0]), "r"(a[1]), "r"(a[2]), "r"(a[3]), "r"(b[0]), "r"(b[1]));
}

// ---------------------------------------------------------------------------
__global__ void zero_kernel() {
    int i = blockIdx.x * blockDim.x + threadIdx.x;
    if (i < 4 * NROWS) g_R[i] = 0.0f;
}

// ---------------------------------------------------------------------------
// Row-normalize h1,h2 -> bf16; diag12 = <h1n_i,h2n_i> in exact fp32
// ---------------------------------------------------------------------------
__global__ void norm_kernel(const float* __restrict__ h1,
                            const float* __restrict__ h2) {
    int gt   = blockIdx.x * blockDim.x + threadIdx.x;
    int w    = gt >> 5;
    int lane = gt & 31;
    if (w >= NROWS) return;

    float4 v1 = ((const float4*)(h1 + (size_t)w * DDIM))[lane];
    float4 v2 = ((const float4*)(h2 + (size_t)w * DDIM))[lane];

    float ss1 = v1.x*v1.x + v1.y*v1.y + v1.z*v1.z + v1.w*v1.w;
    float ss2 = v2.x*v2.x + v2.y*v2.y + v2.z*v2.z + v2.w*v2.w;
    float dt  = v1.x*v2.x + v1.y*v2.y + v1.z*v2.z + v1.w*v2.w;

    #pragma unroll
    for (int m = 16; m > 0; m >>= 1) {
        ss1 += __shfl_xor_sync(0xffffffffu, ss1, m);
        ss2 += __shfl_xor_sync(0xffffffffu, ss2, m);
        dt  += __shfl_xor_sync(0xffffffffu, dt,  m);
    }

    float inv1 = 1.0f / fmaxf(sqrtf(ss1), 1e-12f);
    float inv2 = 1.0f / fmaxf(sqrtf(ss2), 1e-12f);

    __nv_bfloat162* o1 = (__nv_bfloat162*)(g_h1b + (size_t)w * DDIM);
    __nv_bfloat162* o2 = (__nv_bfloat162*)(g_h2b + (size_t)w * DDIM);
    o1[lane * 2 + 0] = __floats2bfloat162_rn(v1.x * inv1, v1.y * inv1);
    o1[lane * 2 + 1] = __floats2bfloat162_rn(v1.z * inv1, v1.w * inv1);
    o2[lane * 2 + 0] = __floats2bfloat162_rn(v2.x * inv2, v2.y * inv2);
    o2[lane * 2 + 1] = __floats2bfloat162_rn(v2.z * inv2, v2.w * inv2);

    if (lane == 0) g_diag[w] = dt * inv1 * inv2;
}

// ---------------------------------------------------------------------------
// Fused HMMA tile GEMM (128x128, K=128, bf16->fp32) + exp(5*s) row/col sums.
// mode 0: S11 (sym, h1,h1 -> R11)   [J>=I tiles only]
// mode 1: S22 (sym, h2,h2 -> R22)   [J>=I tiles only]
// mode 2: S12 (h1,h2; rowsum->R12row, colsum->R12col)
// 8 warps: warp grid 2(M) x 4(N), warp tile 64x32.
// SMEM: A,B tiles [128][128] bf16, 256B rows, xor-swizzled 16B chunks.
// ---------------------------------------------------------------------------
#define SM_A 0
#define SM_B 32768
#define SM_TOTAL 65536

__global__ void __launch_bounds__(256, 2) mma_exp_kernel() {
    extern __shared__ char smem[];
    const uint32_t sb = smem_u32(smem);

    int tid  = threadIdx.x;
    int wid  = tid >> 5;
    int lane = tid & 31;
    int J = blockIdx.x, I = blockIdx.y, mat = blockIdx.z;

    bool sym = (mat != 2);
    if (sym && J < I) return;

    const __nv_bfloat16* Ag = (mat == 1) ? g_h2b : g_h1b;
    const __nv_bfloat16* Bg = (mat == 0) ? g_h1b : g_h2b;
    float* Rrow; float* Rcol;
    if (mat == 0)      { Rrow = g_R;             Rcol = Rrow; }
    else if (mat == 1) { Rrow = g_R + 3*NROWS;   Rcol = Rrow; }
    else               { Rrow = g_R + NROWS;     Rcol = g_R + 2*NROWS; }

    // ---- Global -> swizzled SMEM (16B chunks; chunk' = c ^ (r&7))
    {
        const uint4* a4 = (const uint4*)(Ag + (size_t)I * TM * DDIM);
        const uint4* b4 = (const uint4*)(Bg + (size_t)J * TN * DDIM);
        #pragma unroll
        for (int it = 0; it < 8; it++) {
            int idx = tid + it * 256;           // 2048 chunks of 16B
            int r = idx >> 4, c = idx & 15;
            uint32_t off = (uint32_t)r * 256u + (uint32_t)((c ^ (r & 7)) << 4);
            *(uint4*)(smem + SM_A + off) = a4[idx];
            *(uint4*)(smem + SM_B + off) = b4[idx];
        }
    }
    __syncthreads();

    int wm = wid >> 2;          // 0..1  (M)
    int wn = wid & 3;           // 0..3  (N)

    float acc[4][4][4];
    #pragma unroll
    for (int mt = 0; mt < 4; mt++)
        #pragma unroll
        for (int nt = 0; nt < 4; nt++)
            #pragma unroll
            for (int v = 0; v < 4; v++) acc[mt][nt][v] = 0.0f;

    // Per-lane ldmatrix row/col-part (fixed across ksteps)
    // A (x4): lane l -> row = wm*64 + mt*16 + (l&15), chunkpart = (l>>4)
    // B (2x x4, 2 ntiles each): lane l -> n = wn*32 + ntpair*16 + (l>>4)*8 + (l&7),
    //                           chunkpart = (l>>3)&1
    int a_r    = wm * 64 + (lane & 15);
    int a_cp   = lane >> 4;
    int b_r    = wn * 32 + ((lane >> 4) << 3) + (lane & 7);
    int b_cp   = (lane >> 3) & 1;

    #pragma unroll
    for (int ks = 0; ks < 8; ks++) {
        int kc = ks * 2;   // chunk base for this kstep (16 halves = 2 chunks)
        uint32_t a[4][4], b[4][2];
        #pragma unroll
        for (int mt = 0; mt < 4; mt++) {
            int r = a_r + mt * 16;
            uint32_t addr = sb + SM_A + (uint32_t)r * 256u
                          + (uint32_t)(((kc + a_cp) ^ (r & 7)) << 4);
            ldsm_x4(a[mt][0], a[mt][1], a[mt][2], a[mt][3], addr);
        }
        #pragma unroll
        for (int np = 0; np < 2; np++) {
            int r = b_r + np * 16;
            uint32_t addr = sb + SM_B + (uint32_t)r * 256u
                          + (uint32_t)(((kc + b_cp) ^ (r & 7)) << 4);
            ldsm_x4(b[np*2][0], b[np*2][1], b[np*2+1][0], b[np*2+1][1], addr);
        }
        #pragma unroll
        for (int mt = 0; mt < 4; mt++)
            #pragma unroll
            for (int nt = 0; nt < 4; nt++)
                mma16816(acc[mt][nt], a[mt], b[nt]);
    }

    // ---- Epilogue: e = exp(5*s) = 2^(s*7.2135), row + col partial sums
    // Fragment: d0,d1 -> row l/4,   cols (l%4)*2, +1
    //           d2,d3 -> row l/4+8, same cols
    const float LOG2E5 = 7.2134752044448170f;
    float rp[4][2], cp[4][2];
    #pragma unroll
    for (int mt = 0; mt < 4; mt++) { rp[mt][0] = 0.f; rp[mt][1] = 0.f; }
    #pragma unroll
    for (int nt = 0; nt < 4; nt++) { cp[nt][0] = 0.f; cp[nt][1] = 0.f; }

    #pragma unroll
    for (int mt = 0; mt < 4; mt++)
        #pragma unroll
        for (int nt = 0; nt < 4; nt++) {
            float e0, e1, e2, e3;
            asm("ex2.approx.f32 %0, %1;" : "=f"(e0) : "f"(acc[mt][nt][0] * LOG2E5));
            asm("ex2.approx.f32 %0, %1;" : "=f"(e1) : "f"(acc[mt][nt][1] * LOG2E5));
            asm("ex2.approx.f32 %0, %1;" : "=f"(e2) : "f"(acc[mt][nt][2] * LOG2E5));
            asm("ex2.approx.f32 %0, %1;" : "=f"(e3) : "f"(acc[mt][nt][3] * LOG2E5));
            rp[mt][0] += e0 + e1;
            rp[mt][1] += e2 + e3;
            cp[nt][0] += e0 + e2;
            cp[nt][1] += e1 + e3;
        }

    // Row sums: reduce over lane%4 (cols) -> every lane has row totals
    #pragma unroll
    for (int mt = 0; mt < 4; mt++)
        #pragma unroll
        for (int h = 0; h < 2; h++) {
            rp[mt][h] += __shfl_xor_sync(0xffffffffu, rp[mt][h], 1);
            rp[mt][h] += __shfl_xor_sync(0xffffffffu, rp[mt][h], 2);
        }
    if ((lane & 3) == 0) {
        int r0 = I * TM + wm * 64 + (lane >> 2);
        #pragma unroll
        for (int mt = 0; mt < 4; mt++) {
            atomicAdd(&Rrow[r0 + mt * 16],     rp[mt][0]);
            atomicAdd(&Rrow[r0 + mt * 16 + 8], rp[mt][1]);
        }
    }

    // Col sums: cross tiles always; sym tiles only strictly above diagonal
    if (!sym || J > I) {
        #pragma unroll
        for (int nt = 0; nt < 4; nt++)
            #pragma unroll
            for (int h = 0; h < 2; h++) {
                cp[nt][h] += __shfl_xor_sync(0xffffffffu, cp[nt][h], 4);
                cp[nt][h] += __shfl_xor_sync(0xffffffffu, cp[nt][h], 8);
                cp[nt][h] += __shfl_xor_sync(0xffffffffu, cp[nt][h], 16);
            }
        if (lane < 4) {
            int c0 = J * TN + wn * 32 + lane * 2;
            #pragma unroll
            for (int nt = 0; nt < 4; nt++) {
                atomicAdd(&Rcol[c0 + nt * 8],     cp[nt][0]);
                atomicAdd(&Rcol[c0 + nt * 8 + 1], cp[nt][1]);
            }
        }
    }
}

// ---------------------------------------------------------------------------
// Final scalar: mean over i of 0.5*(log(neg1)+log(neg2)) - 5*diag12
// neg1 = R11 + R12row - e^5 ; neg2 = R22 + R12col - e^5
// ---------------------------------------------------------------------------
__global__ void final_kernel(float* out) {
    __shared__ float sm[256];
    int t = threadIdx.x;
    const float E5 = 148.4131591f;   // exp(1/tau), tau = 0.2

    float s = 0.0f;
    for (int i = t; i < NROWS; i += 256) {
        float n1 = g_R[i]             + g_R[NROWS + i]     - E5;
        float n2 = g_R[3 * NROWS + i] + g_R[2 * NROWS + i] - E5;
        s += 0.5f * (logf(n1) + logf(n2)) - 5.0f * g_diag[i];
    }
    sm[t] = s;
    __syncthreads();
    #pragma unroll
    for (int o = 128; o > 0; o >>= 1) {
        if (t < o) sm[t] += sm[t + o];
        __syncthreads();
    }
    if (t == 0) out[0] = sm[0] * (1.0f / NROWS);
}

// ---------------------------------------------------------------------------
extern "C" void kernel_launch(void* const* d_in, const int* in_sizes, int n_in,
                              void* d_out, int out_size) {
    const float* h1 = (const float*)d_in[0];
    const float* h2 = (const float*)d_in[1];
    float* out = (float*)d_out;

    cudaFuncSetAttribute(mma_exp_kernel,
                         cudaFuncAttributeMaxDynamicSharedMemorySize, SM_TOTAL);

    zero_kernel<<<(4 * NROWS + 255) / 256, 256>>>();
    norm_kernel<<<(NROWS * 32) / 256, 256>>>(h1, h2);

    dim3 grid(NROWS / TN, NROWS / TM, 3);   // 64 x 64 x 3 (sym modes skip J<I)
    mma_exp_kernel<<<grid, 256, SM_TOTAL>>>();

    final_kernel<<<1, 256>>>(out);
}

// round 4
// speedup vs baseline: 5.8164x; 1.0239x over previous
#include <cuda_runtime.h>
#include <cuda_bf16.h>
#include <math.h>
#include <stdint.h>

#define NROWS 8192
#define DDIM  128
#define TM    128
#define TN    128

// Scratch (__device__ globals: allocation-free rule)
__device__ uint8_t g_h1q[NROWS * DDIM];   // e4m3 of 4*normalized h1
__device__ uint8_t g_h2q[NROWS * DDIM];   // e4m3 of 4*normalized h2
__device__ float g_R[4 * NROWS];          // [R11 | R12row | R12col | R22]
__device__ float g_diag[NROWS];

// ---------------------------------------------------------------------------
__device__ __forceinline__ uint32_t smem_u32(const void* p) {
    uint32_t a;
    asm("{ .reg .u64 t; cvta.to.shared.u64 t, %1; cvt.u32.u64 %0, t; }"
        : "=r"(a) : "l"(p));
    return a;
}

__device__ __forceinline__ void ldsm_x4(uint32_t& r0, uint32_t& r1,
                                        uint32_t& r2, uint32_t& r3, uint32_t addr) {
    asm volatile("ldmatrix.sync.aligned.m8n8.x4.shared.b16 {%0,%1,%2,%3}, [%4];"
                 : "=r"(r0), "=r"(r1), "=r"(r2), "=r"(r3) : "r"(addr));
}

__device__ __forceinline__ void mma_fp8(float* d, const uint32_t* a, const uint32_t* b) {
    asm volatile(
        "mma.sync.aligned.m16n8k32.row.col.f32.e4m3.e4m3.f32 "
        "{%0,%1,%2,%3}, {%4,%5,%6,%7}, {%8,%9}, {%0,%1,%2,%3};"
        : "+f"(d[0]), "+f"(d[1]), "+f"(d[2]), "+f"(d[3])
        : "r"(a[0]), "r"(a[1]), "r"(a[2]), "r"(a[3]), "r"(b[0]), "r"(b[1]));
}

// Pack 4 floats -> 4 e4m3 bytes (little-endian order e0,e1,e2,e3)
__device__ __forceinline__ uint32_t pack_e4m3x4(float e0, float e1, float e2, float e3) {
    uint32_t r;
    asm("{ .reg .b16 lo, hi;\n\t"
        "cvt.rn.satfinite.e4m3x2.f32 lo, %2, %1;\n\t"
        "cvt.rn.satfinite.e4m3x2.f32 hi, %4, %3;\n\t"
        "mov.b32 %0, {lo, hi}; }"
        : "=r"(r) : "f"(e0), "f"(e1), "f"(e2), "f"(e3));
    return r;
}

// ---------------------------------------------------------------------------
// Row-normalize -> e4m3 (scaled x4); diag12 exact fp32; also zero g_R and out.
// ---------------------------------------------------------------------------
__global__ void norm_kernel(const float* __restrict__ h1,
                            const float* __restrict__ h2,
                            float* __restrict__ out) {
    int gt   = blockIdx.x * blockDim.x + threadIdx.x;
    int w    = gt >> 5;
    int lane = gt & 31;

    if (gt < 4 * NROWS) g_R[gt] = 0.0f;
    if (gt == 0) out[0] = 0.0f;
    if (w >= NROWS) return;

    float4 v1 = ((const float4*)(h1 + (size_t)w * DDIM))[lane];
    float4 v2 = ((const float4*)(h2 + (size_t)w * DDIM))[lane];

    float ss1 = v1.x*v1.x + v1.y*v1.y + v1.z*v1.z + v1.w*v1.w;
    float ss2 = v2.x*v2.x + v2.y*v2.y + v2.z*v2.z + v2.w*v2.w;
    float dt  = v1.x*v2.x + v1.y*v2.y + v1.z*v2.z + v1.w*v2.w;

    #pragma unroll
    for (int m = 16; m > 0; m >>= 1) {
        ss1 += __shfl_xor_sync(0xffffffffu, ss1, m);
        ss2 += __shfl_xor_sync(0xffffffffu, ss2, m);
        dt  += __shfl_xor_sync(0xffffffffu, dt,  m);
    }

    // x4 scale lifts typical entries (~0.09) well into e4m3 normal range.
    float inv1 = 4.0f / fmaxf(sqrtf(ss1), 1e-12f);
    float inv2 = 4.0f / fmaxf(sqrtf(ss2), 1e-12f);

    ((uint32_t*)(g_h1q + (size_t)w * DDIM))[lane] =
        pack_e4m3x4(v1.x*inv1, v1.y*inv1, v1.z*inv1, v1.w*inv1);
    ((uint32_t*)(g_h2q + (size_t)w * DDIM))[lane] =
        pack_e4m3x4(v2.x*inv2, v2.y*inv2, v2.z*inv2, v2.w*inv2);

    if (lane == 0) g_diag[w] = (dt * inv1 * inv2) * 0.0625f;  // undo 4*4
}

// ---------------------------------------------------------------------------
// Fused FP8 HMMA tile GEMM (128x128, K=128) + exp(5*s) row/col sums.
// acc = 16*s (operands scaled x4).  e = 2^(acc * 5*log2(e)/16)
// mode 0: S11 (sym, J>=I)  mode 1: S22 (sym, J>=I)  mode 2: S12 (full)
// 8 warps: 2(M) x 4(N), warp tile 64x32. SMEM rows = 128 B (K=128 e4m3),
// 8x16B chunks, xor-swizzled (c ^ (r&7)).
// ---------------------------------------------------------------------------
#define SM_A 0
#define SM_B 16384
#define SM_TOTAL 32768

__global__ void __launch_bounds__(256, 2) mma_exp_kernel() {
    extern __shared__ char smem[];
    const uint32_t sb = smem_u32(smem);

    int tid  = threadIdx.x;
    int wid  = tid >> 5;
    int lane = tid & 31;
    int J = blockIdx.x, I = blockIdx.y, mat = blockIdx.z;

    bool sym = (mat != 2);
    if (sym && J < I) return;

    const uint8_t* Ag = (mat == 1) ? g_h2q : g_h1q;
    const uint8_t* Bg = (mat == 0) ? g_h1q : g_h2q;
    float* Rrow; float* Rcol;
    if (mat == 0)      { Rrow = g_R;             Rcol = Rrow; }
    else if (mat == 1) { Rrow = g_R + 3*NROWS;   Rcol = Rrow; }
    else               { Rrow = g_R + NROWS;     Rcol = g_R + 2*NROWS; }

    // ---- Global -> swizzled SMEM: 1024 chunks of 16B per tile, 4 iters
    {
        const uint4* a4 = (const uint4*)(Ag + (size_t)I * TM * DDIM);
        const uint4* b4 = (const uint4*)(Bg + (size_t)J * TN * DDIM);
        #pragma unroll
        for (int it = 0; it < 4; it++) {
            int idx = tid + it * 256;
            int r = idx >> 3, c = idx & 7;
            uint32_t off = (uint32_t)r * 128u + (uint32_t)((c ^ (r & 7)) << 4);
            *(uint4*)(smem + SM_A + off) = a4[idx];
            *(uint4*)(smem + SM_B + off) = b4[idx];
        }
    }
    __syncthreads();

    int wm = wid >> 2;          // 0..1  (M)
    int wn = wid & 3;           // 0..3  (N)

    float acc[4][4][4];
    #pragma unroll
    for (int mt = 0; mt < 4; mt++)
        #pragma unroll
        for (int nt = 0; nt < 4; nt++)
            #pragma unroll
            for (int v = 0; v < 4; v++) acc[mt][nt][v] = 0.0f;

    int a_r  = wm * 64 + (lane & 15);
    int a_cp = lane >> 4;
    int b_r  = wn * 32 + ((lane >> 4) << 3) + (lane & 7);
    int b_cp = (lane >> 3) & 1;

    #pragma unroll
    for (int ks = 0; ks < 4; ks++) {
        int kc = ks * 2;   // 32 fp8 bytes per kstep = 2 chunks
        uint32_t a[4][4], b[4][2];
        #pragma unroll
        for (int mt = 0; mt < 4; mt++) {
            int r = a_r + mt * 16;
            uint32_t addr = sb + SM_A + (uint32_t)r * 128u
                          + (uint32_t)(((kc + a_cp) ^ (r & 7)) << 4);
            ldsm_x4(a[mt][0], a[mt][1], a[mt][2], a[mt][3], addr);
        }
        #pragma unroll
        for (int np = 0; np < 2; np++) {
            int r = b_r + np * 16;
            uint32_t addr = sb + SM_B + (uint32_t)r * 128u
                          + (uint32_t)(((kc + b_cp) ^ (r & 7)) << 4);
            ldsm_x4(b[np*2][0], b[np*2][1], b[np*2+1][0], b[np*2+1][1], addr);
        }
        #pragma unroll
        for (int mt = 0; mt < 4; mt++)
            #pragma unroll
            for (int nt = 0; nt < 4; nt++)
                mma_fp8(acc[mt][nt], a[mt], b[nt]);
    }

    // ---- Epilogue: e = 2^(acc * 5*log2(e)/16); row + col partial sums
    const float SCL = 0.45084220027780106f;  // 5*log2(e)/16
    float rp[4][2], cp[4][2];
    #pragma unroll
    for (int mt = 0; mt < 4; mt++) { rp[mt][0] = 0.f; rp[mt][1] = 0.f; }
    #pragma unroll
    for (int nt = 0; nt < 4; nt++) { cp[nt][0] = 0.f; cp[nt][1] = 0.f; }

    #pragma unroll
    for (int mt = 0; mt < 4; mt++)
        #pragma unroll
        for (int nt = 0; nt < 4; nt++) {
            float e0, e1, e2, e3;
            asm("ex2.approx.f32 %0, %1;" : "=f"(e0) : "f"(acc[mt][nt][0] * SCL));
            asm("ex2.approx.f32 %0, %1;" : "=f"(e1) : "f"(acc[mt][nt][1] * SCL));
            asm("ex2.approx.f32 %0, %1;" : "=f"(e2) : "f"(acc[mt][nt][2] * SCL));
            asm("ex2.approx.f32 %0, %1;" : "=f"(e3) : "f"(acc[mt][nt][3] * SCL));
            rp[mt][0] += e0 + e1;
            rp[mt][1] += e2 + e3;
            cp[nt][0] += e0 + e2;
            cp[nt][1] += e1 + e3;
        }

    #pragma unroll
    for (int mt = 0; mt < 4; mt++)
        #pragma unroll
        for (int h = 0; h < 2; h++) {
            rp[mt][h] += __shfl_xor_sync(0xffffffffu, rp[mt][h], 1);
            rp[mt][h] += __shfl_xor_sync(0xffffffffu, rp[mt][h], 2);
        }
    if ((lane & 3) == 0) {
        int r0 = I * TM + wm * 64 + (lane >> 2);
        #pragma unroll
        for (int mt = 0; mt < 4; mt++) {
            atomicAdd(&Rrow[r0 + mt * 16],     rp[mt][0]);
            atomicAdd(&Rrow[r0 + mt * 16 + 8], rp[mt][1]);
        }
    }

    if (!sym || J > I) {
        #pragma unroll
        for (int nt = 0; nt < 4; nt++)
            #pragma unroll
            for (int h = 0; h < 2; h++) {
                cp[nt][h] += __shfl_xor_sync(0xffffffffu, cp[nt][h], 4);
                cp[nt][h] += __shfl_xor_sync(0xffffffffu, cp[nt][h], 8);
                cp[nt][h] += __shfl_xor_sync(0xffffffffu, cp[nt][h], 16);
            }
        if (lane < 4) {
            int c0 = J * TN + wn * 32 + lane * 2;
            #pragma unroll
            for (int nt = 0; nt < 4; nt++) {
                atomicAdd(&Rcol[c0 + nt * 8],     cp[nt][0]);
                atomicAdd(&Rcol[c0 + nt * 8 + 1], cp[nt][1]);
            }
        }
    }
}

// ---------------------------------------------------------------------------
// Final scalar, parallel: 32 blocks x 256 threads, one row per thread.
// mean_i [ 0.5*(log(neg1)+log(neg2)) - 5*diag12 ]
// ---------------------------------------------------------------------------
__global__ void final_kernel(float* out) {
    __shared__ float sm[256];
    int t = threadIdx.x;
    int i = blockIdx.x * 256 + t;
    const float E5 = 148.4131591f;   // exp(1/tau), tau = 0.2

    float n1 = g_R[i]             + g_R[NROWS + i]     - E5;
    float n2 = g_R[3 * NROWS + i] + g_R[2 * NROWS + i] - E5;
    float s  = 0.5f * (logf(n1) + logf(n2)) - 5.0f * g_diag[i];

    sm[t] = s;
    __syncthreads();
    #pragma unroll
    for (int o = 128; o > 0; o >>= 1) {
        if (t < o) sm[t] += sm[t + o];
        __syncthreads();
    }
    if (t == 0) atomicAdd(out, sm[0] * (1.0f / NROWS));
}

// ---------------------------------------------------------------------------
extern "C" void kernel_launch(void* const* d_in, const int* in_sizes, int n_in,
                              void* d_out, int out_size) {
    const float* h1 = (const float*)d_in[0];
    const float* h2 = (const float*)d_in[1];
    float* out = (float*)d_out;

    cudaFuncSetAttribute(mma_exp_kernel,
                         cudaFuncAttributeMaxDynamicSharedMemorySize, SM_TOTAL);

    norm_kernel<<<(NROWS * 32) / 256, 256>>>(h1, h2, out);

    dim3 grid(NROWS / TN, NROWS / TM, 3);   // 64 x 64 x 3 (sym modes skip J<I)
    mma_exp_kernel<<<grid, 256, SM_TOTAL>>>();

    final_kernel<<<NROWS / 256, 256>>>(out);
}

// round 5
// speedup vs baseline: 6.0238x; 1.0356x over previous
#include <cuda_runtime.h>
#include <cuda_bf16.h>
#include <math.h>
#include <stdint.h>

#define NROWS 8192
#define DDIM  128
#define NT    64          // 8192/128 tiles per side
#define NPAIR 2080        // 64*65/2

// Scratch (__device__ globals: allocation-free rule)
__device__ uint8_t g_h1q[NROWS * DDIM];   // e4m3 of 4*normalized h1
__device__ uint8_t g_h2q[NROWS * DDIM];   // e4m3 of 4*normalized h2
__device__ float g_R[4 * NROWS];          // [R11 | R12row | R12col | R22]
__device__ float g_diag[NROWS];

// ---------------------------------------------------------------------------
__device__ __forceinline__ uint32_t smem_u32(const void* p) {
    uint32_t a;
    asm("{ .reg .u64 t; cvta.to.shared.u64 t, %1; cvt.u32.u64 %0, t; }"
        : "=r"(a) : "l"(p));
    return a;
}

__device__ __forceinline__ void ldsm_x4(uint32_t& r0, uint32_t& r1,
                                        uint32_t& r2, uint32_t& r3, uint32_t addr) {
    asm volatile("ldmatrix.sync.aligned.m8n8.x4.shared.b16 {%0,%1,%2,%3}, [%4];"
                 : "=r"(r0), "=r"(r1), "=r"(r2), "=r"(r3) : "r"(addr));
}

__device__ __forceinline__ void mma_fp8(float* d, const uint32_t* a, const uint32_t* b) {
    asm volatile(
        "mma.sync.aligned.m16n8k32.row.col.f32.e4m3.e4m3.f32 "
        "{%0,%1,%2,%3}, {%4,%5,%6,%7}, {%8,%9}, {%0,%1,%2,%3};"
        : "+f"(d[0]), "+f"(d[1]), "+f"(d[2]), "+f"(d[3])
        : "r"(a[0]), "r"(a[1]), "r"(a[2]), "r"(a[3]), "r"(b[0]), "r"(b[1]));
}

// Pack 4 floats -> 4 e4m3 bytes
__device__ __forceinline__ uint32_t pack_e4m3x4(float e0, float e1, float e2, float e3) {
    uint32_t r;
    asm("{ .reg .b16 lo, hi;\n\t"
        "cvt.rn.satfinite.e4m3x2.f32 lo, %2, %1;\n\t"
        "cvt.rn.satfinite.e4m3x2.f32 hi, %4, %3;\n\t"
        "mov.b32 %0, {lo, hi}; }"
        : "=r"(r) : "f"(e0), "f"(e1), "f"(e2), "f"(e3));
    return r;
}

// ---------------------------------------------------------------------------
// Row-normalize -> e4m3 (scaled x4); diag12 exact fp32; zero g_R and out.
// ---------------------------------------------------------------------------
__global__ void norm_kernel(const float* __restrict__ h1,
                            const float* __restrict__ h2,
                            float* __restrict__ out) {
    int gt   = blockIdx.x * blockDim.x + threadIdx.x;
    int w    = gt >> 5;
    int lane = gt & 31;

    if (gt < 4 * NROWS) g_R[gt] = 0.0f;
    if (gt == 0) out[0] = 0.0f;
    if (w >= NROWS) return;

    float4 v1 = ((const float4*)(h1 + (size_t)w * DDIM))[lane];
    float4 v2 = ((const float4*)(h2 + (size_t)w * DDIM))[lane];

    float ss1 = v1.x*v1.x + v1.y*v1.y + v1.z*v1.z + v1.w*v1.w;
    float ss2 = v2.x*v2.x + v2.y*v2.y + v2.z*v2.z + v2.w*v2.w;
    float dt  = v1.x*v2.x + v1.y*v2.y + v1.z*v2.z + v1.w*v2.w;

    #pragma unroll
    for (int m = 16; m > 0; m >>= 1) {
        ss1 += __shfl_xor_sync(0xffffffffu, ss1, m);
        ss2 += __shfl_xor_sync(0xffffffffu, ss2, m);
        dt  += __shfl_xor_sync(0xffffffffu, dt,  m);
    }

    float inv1 = 4.0f / fmaxf(sqrtf(ss1), 1e-12f);
    float inv2 = 4.0f / fmaxf(sqrtf(ss2), 1e-12f);

    ((uint32_t*)(g_h1q + (size_t)w * DDIM))[lane] =
        pack_e4m3x4(v1.x*inv1, v1.y*inv1, v1.z*inv1, v1.w*inv1);
    ((uint32_t*)(g_h2q + (size_t)w * DDIM))[lane] =
        pack_e4m3x4(v2.x*inv2, v2.y*inv2, v2.z*inv2, v2.w*inv2);

    if (lane == 0) g_diag[w] = (dt * inv1 * inv2) * 0.0625f;  // undo 4*4
}

// ---------------------------------------------------------------------------
// Pair-CTA kernel: one CTA per tile pair (I<=J). Loads h1[I],h2[I],h1[J],h2[J]
// (fp8, 16KB each), then computes up to 4 fused GEMM+exp+rowsum/colsum passes:
//   g0: h1[I]*h1[J]^T (S11): row->R11[I], col->R11[J] (J>I)
//   g1: h2[I]*h2[J]^T (S22): row->R22[I], col->R22[J] (J>I)
//   g2: h1[I]*h2[J]^T (S12): row->R12row[I], col->R12col[J]
//   g3: h2[I]*h1[J]^T (S21 = S12(J,I)^T): row->R12col[I], col->R12row[J] (J>I only)
// 8 warps: 2(M) x 4(N), warp tile 64x32. SMEM rows 128B, xor-swizzled 16B chunks.
// ---------------------------------------------------------------------------
#define SM_TILE 16384
#define SM_TOTAL (4 * SM_TILE)

__global__ void __launch_bounds__(256, 2) mma_exp_kernel() {
    extern __shared__ char smem[];
    const uint32_t sb = smem_u32(smem);

    int tid  = threadIdx.x;
    int wid  = tid >> 5;
    int lane = tid & 31;

    // Decode triangular pair index -> (I, J), I<=J
    int p = blockIdx.x, I = 0;
    while (p >= NT - I) { p -= NT - I; I++; }
    int J = I + p;
    bool offd = (J > I);

    // ---- Load 4 tiles (h1[I], h2[I], h1[J], h2[J]) into swizzled SMEM
    {
        const uint4* base[4] = {
            (const uint4*)(g_h1q + (size_t)I * 128 * DDIM),
            (const uint4*)(g_h2q + (size_t)I * 128 * DDIM),
            (const uint4*)(g_h1q + (size_t)J * 128 * DDIM),
            (const uint4*)(g_h2q + (size_t)J * 128 * DDIM)
        };
        #pragma unroll
        for (int it = 0; it < 16; it++) {
            int tile = it >> 2;
            int lidx = tid + (it & 3) * 256;      // 0..1023 chunk within tile
            int r = lidx >> 3, c = lidx & 7;
            uint32_t off = (uint32_t)tile * SM_TILE + (uint32_t)r * 128u
                         + (uint32_t)((c ^ (r & 7)) << 4);
            *(uint4*)(smem + off) = base[tile][lidx];
        }
    }
    __syncthreads();

    int wm = wid >> 2;          // 0..1  (M)
    int wn = wid & 3;           // 0..3  (N)
    int a_r  = wm * 64 + (lane & 15);
    int a_cp = lane >> 4;
    int b_r  = wn * 32 + ((lane >> 4) << 3) + (lane & 7);
    int b_cp = (lane >> 3) & 1;

    const float SCL = 0.45084220027780106f;  // 5*log2(e)/16 (acc = 16*s)

    #pragma unroll 1
    for (int g = 0; g < 4; g++) {
        if (g == 3 && !offd) break;

        // smem tile offsets: A from I-side (tiles 0/1), B from J-side (2/3)
        uint32_t As = (uint32_t)(g & 1) * SM_TILE;                       // g0:h1I g1:h2I g2:h1I g3:h2I
        uint32_t Bs = (2u + (uint32_t)((g == 1 || g == 2) ? 1 : 0)) * SM_TILE;
        if (g == 2) As = 0;  // explicit (g&1 gives 0 for g2 already; keep clarity)

        float* Rrow; float* Rcol; bool docol;
        if (g == 0)      { Rrow = g_R + I*128;             Rcol = g_R + J*128;             docol = offd; }
        else if (g == 1) { Rrow = g_R + 3*NROWS + I*128;   Rcol = g_R + 3*NROWS + J*128;   docol = offd; }
        else if (g == 2) { Rrow = g_R + NROWS + I*128;     Rcol = g_R + 2*NROWS + J*128;   docol = true; }
        else             { Rrow = g_R + 2*NROWS + I*128;   Rcol = g_R + NROWS + J*128;     docol = true; }

        float acc[4][4][4];
        #pragma unroll
        for (int mt = 0; mt < 4; mt++)
            #pragma unroll
            for (int nt = 0; nt < 4; nt++)
                #pragma unroll
                for (int v = 0; v < 4; v++) acc[mt][nt][v] = 0.0f;

        #pragma unroll
        for (int ks = 0; ks < 4; ks++) {
            int kc = ks * 2;
            uint32_t a[4][4], b[4][2];
            #pragma unroll
            for (int mt = 0; mt < 4; mt++) {
                int r = a_r + mt * 16;
                uint32_t addr = sb + As + (uint32_t)r * 128u
                              + (uint32_t)(((kc + a_cp) ^ (r & 7)) << 4);
                ldsm_x4(a[mt][0], a[mt][1], a[mt][2], a[mt][3], addr);
            }
            #pragma unroll
            for (int np = 0; np < 2; np++) {
                int r = b_r + np * 16;
                uint32_t addr = sb + Bs + (uint32_t)r * 128u
                              + (uint32_t)(((kc + b_cp) ^ (r & 7)) << 4);
                ldsm_x4(b[np*2][0], b[np*2][1], b[np*2+1][0], b[np*2+1][1], addr);
            }
            #pragma unroll
            for (int mt = 0; mt < 4; mt++)
                #pragma unroll
                for (int nt = 0; nt < 4; nt++)
                    mma_fp8(acc[mt][nt], a[mt], b[nt]);
        }

        // ---- Epilogue: e = 2^(acc*SCL); row + col partial sums
        float rp[4][2], cp[4][2];
        #pragma unroll
        for (int mt = 0; mt < 4; mt++) { rp[mt][0] = 0.f; rp[mt][1] = 0.f; }
        #pragma unroll
        for (int nt = 0; nt < 4; nt++) { cp[nt][0] = 0.f; cp[nt][1] = 0.f; }

        #pragma unroll
        for (int mt = 0; mt < 4; mt++)
            #pragma unroll
            for (int nt = 0; nt < 4; nt++) {
                float e0, e1, e2, e3;
                asm("ex2.approx.f32 %0, %1;" : "=f"(e0) : "f"(acc[mt][nt][0] * SCL));
                asm("ex2.approx.f32 %0, %1;" : "=f"(e1) : "f"(acc[mt][nt][1] * SCL));
                asm("ex2.approx.f32 %0, %1;" : "=f"(e2) : "f"(acc[mt][nt][2] * SCL));
                asm("ex2.approx.f32 %0, %1;" : "=f"(e3) : "f"(acc[mt][nt][3] * SCL));
                rp[mt][0] += e0 + e1;
                rp[mt][1] += e2 + e3;
                cp[nt][0] += e0 + e2;
                cp[nt][1] += e1 + e3;
            }

        #pragma unroll
        for (int mt = 0; mt < 4; mt++)
            #pragma unroll
            for (int h = 0; h < 2; h++) {
                rp[mt][h] += __shfl_xor_sync(0xffffffffu, rp[mt][h], 1);
                rp[mt][h] += __shfl_xor_sync(0xffffffffu, rp[mt][h], 2);
            }
        if ((lane & 3) == 0) {
            int r0 = wm * 64 + (lane >> 2);
            #pragma unroll
            for (int mt = 0; mt < 4; mt++) {
                atomicAdd(&Rrow[r0 + mt * 16],     rp[mt][0]);
                atomicAdd(&Rrow[r0 + mt * 16 + 8], rp[mt][1]);
            }
        }

        if (docol) {
            #pragma unroll
            for (int nt = 0; nt < 4; nt++)
                #pragma unroll
                for (int h = 0; h < 2; h++) {
                    cp[nt][h] += __shfl_xor_sync(0xffffffffu, cp[nt][h], 4);
                    cp[nt][h] += __shfl_xor_sync(0xffffffffu, cp[nt][h], 8);
                    cp[nt][h] += __shfl_xor_sync(0xffffffffu, cp[nt][h], 16);
                }
            if (lane < 4) {
                int c0 = wn * 32 + lane * 2;
                #pragma unroll
                for (int nt = 0; nt < 4; nt++) {
                    atomicAdd(&Rcol[c0 + nt * 8],     cp[nt][0]);
                    atomicAdd(&Rcol[c0 + nt * 8 + 1], cp[nt][1]);
                }
            }
        }
    }
}

// ---------------------------------------------------------------------------
// Final scalar: 32 blocks x 256 threads, one row per thread.
// ---------------------------------------------------------------------------
__global__ void final_kernel(float* out) {
    __shared__ float sm[256];
    int t = threadIdx.x;
    int i = blockIdx.x * 256 + t;
    const float E5 = 148.4131591f;   // exp(1/tau), tau = 0.2

    float n1 = g_R[i]             + g_R[NROWS + i]     - E5;
    float n2 = g_R[3 * NROWS + i] + g_R[2 * NROWS + i] - E5;
    float s  = 0.5f * (logf(n1) + logf(n2)) - 5.0f * g_diag[i];

    sm[t] = s;
    __syncthreads();
    #pragma unroll
    for (int o = 128; o > 0; o >>= 1) {
        if (t < o) sm[t] += sm[t + o];
        __syncthreads();
    }
    if (t == 0) atomicAdd(out, sm[0] * (1.0f / NROWS));
}

// ---------------------------------------------------------------------------
extern "C" void kernel_launch(void* const* d_in, const int* in_sizes, int n_in,
                              void* d_out, int out_size) {
    const float* h1 = (const float*)d_in[0];
    const float* h2 = (const float*)d_in[1];
    float* out = (float*)d_out;

    cudaFuncSetAttribute(mma_exp_kernel,
                         cudaFuncAttributeMaxDynamicSharedMemorySize, SM_TOTAL);

    norm_kernel<<<(NROWS * 32) / 256, 256>>>(h1, h2, out);
    mma_exp_kernel<<<NPAIR, 256, SM_TOTAL>>>();
    final_kernel<<<NROWS / 256, 256>>>(out);
}

// round 6
// speedup vs baseline: 6.0357x; 1.0020x over previous
#include <cuda_runtime.h>
#include <cuda_bf16.h>
#include <math.h>
#include <stdint.h>

#define NROWS 8192
#define DDIM  128
#define NT    64          // 8192/128 tiles per side
#define NPAIR 2080        // 64*65/2

// Scratch (__device__ globals: allocation-free rule)
__device__ uint8_t g_h1q[NROWS * DDIM];   // e4m3 of c*normalized h1, c=sqrt(5*log2 e)
__device__ uint8_t g_h2q[NROWS * DDIM];
__device__ float g_R[4 * NROWS];          // [R11 | R12row | R12col | R22]
__device__ float g_diag[NROWS];

// ---------------------------------------------------------------------------
__device__ __forceinline__ uint32_t smem_u32(const void* p) {
    uint32_t a;
    asm("{ .reg .u64 t; cvta.to.shared.u64 t, %1; cvt.u32.u64 %0, t; }"
        : "=r"(a) : "l"(p));
    return a;
}

__device__ __forceinline__ void ldsm_x4(uint32_t& r0, uint32_t& r1,
                                        uint32_t& r2, uint32_t& r3, uint32_t addr) {
    asm volatile("ldmatrix.sync.aligned.m8n8.x4.shared.b16 {%0,%1,%2,%3}, [%4];"
                 : "=r"(r0), "=r"(r1), "=r"(r2), "=r"(r3) : "r"(addr));
}

__device__ __forceinline__ void mma_fp8(float* d, const uint32_t* a, const uint32_t* b) {
    asm volatile(
        "mma.sync.aligned.m16n8k32.row.col.f32.e4m3.e4m3.f32 "
        "{%0,%1,%2,%3}, {%4,%5,%6,%7}, {%8,%9}, {%0,%1,%2,%3};"
        : "+f"(d[0]), "+f"(d[1]), "+f"(d[2]), "+f"(d[3])
        : "r"(a[0]), "r"(a[1]), "r"(a[2]), "r"(a[3]), "r"(b[0]), "r"(b[1]));
}

__device__ __forceinline__ uint32_t pack_e4m3x4(float e0, float e1, float e2, float e3) {
    uint32_t r;
    asm("{ .reg .b16 lo, hi;\n\t"
        "cvt.rn.satfinite.e4m3x2.f32 lo, %2, %1;\n\t"
        "cvt.rn.satfinite.e4m3x2.f32 hi, %4, %3;\n\t"
        "mov.b32 %0, {lo, hi}; }"
        : "=r"(r) : "f"(e0), "f"(e1), "f"(e2), "f"(e3));
    return r;
}

// ---------------------------------------------------------------------------
// Row-normalize -> e4m3 scaled by C = sqrt(5*log2(e)); exact fp32 diag;
// zero g_R and out.  With this scale, acc = 5*log2(e)*s, so exp(5s)=2^acc.
// ---------------------------------------------------------------------------
__global__ void norm_kernel(const float* __restrict__ h1,
                            const float* __restrict__ h2,
                            float* __restrict__ out) {
    int gt   = blockIdx.x * blockDim.x + threadIdx.x;
    int w    = gt >> 5;
    int lane = gt & 31;

    if (gt < 4 * NROWS) g_R[gt] = 0.0f;
    if (gt == 0) out[0] = 0.0f;
    if (w >= NROWS) return;

    float4 v1 = ((const float4*)(h1 + (size_t)w * DDIM))[lane];
    float4 v2 = ((const float4*)(h2 + (size_t)w * DDIM))[lane];

    float ss1 = v1.x*v1.x + v1.y*v1.y + v1.z*v1.z + v1.w*v1.w;
    float ss2 = v2.x*v2.x + v2.y*v2.y + v2.z*v2.z + v2.w*v2.w;
    float dt  = v1.x*v2.x + v1.y*v2.y + v1.z*v2.z + v1.w*v2.w;

    #pragma unroll
    for (int m = 16; m > 0; m >>= 1) {
        ss1 += __shfl_xor_sync(0xffffffffu, ss1, m);
        ss2 += __shfl_xor_sync(0xffffffffu, ss2, m);
        dt  += __shfl_xor_sync(0xffffffffu, dt,  m);
    }

    const float C = 2.6857914f;   // sqrt(5*log2(e))
    float in1 = 1.0f / fmaxf(sqrtf(ss1), 1e-12f);
    float in2 = 1.0f / fmaxf(sqrtf(ss2), 1e-12f);
    float s1 = C * in1, s2 = C * in2;

    ((uint32_t*)(g_h1q + (size_t)w * DDIM))[lane] =
        pack_e4m3x4(v1.x*s1, v1.y*s1, v1.z*s1, v1.w*s1);
    ((uint32_t*)(g_h2q + (size_t)w * DDIM))[lane] =
        pack_e4m3x4(v2.x*s2, v2.y*s2, v2.z*s2, v2.w*s2);

    if (lane == 0) g_diag[w] = dt * in1 * in2;
}

// ---------------------------------------------------------------------------
// Pair-CTA kernel, strip-pipelined. One CTA per tile pair (I<=J).
// Per GEMM g: preload all B fragments (32 regs), then 4 independent
// 16-row strips: LDSM(A) -> 16 MMA -> 16 ex2 + sums. Strips overlap
// MMA / MUFU / FMA pipes within one warp via scoreboarding.
//   g0: h1[I]*h1[J]^T  row->R11[I],  col->R11[J] (J>I)
//   g1: h2[I]*h2[J]^T  row->R22[I],  col->R22[J] (J>I)
//   g2: h1[I]*h2[J]^T  row->R12r[I], col->R12c[J]
//   g3: h2[I]*h1[J]^T  row->R12c[I], col->R12r[J] (J>I only)
// ---------------------------------------------------------------------------
#define SM_TILE 16384
#define SM_TOTAL (4 * SM_TILE)

__global__ void __launch_bounds__(256, 2) mma_exp_kernel() {
    extern __shared__ char smem[];
    const uint32_t sb = smem_u32(smem);

    int tid  = threadIdx.x;
    int wid  = tid >> 5;
    int lane = tid & 31;

    // Decode triangular pair index -> (I, J), I<=J
    int p = blockIdx.x, I = 0;
    while (p >= NT - I) { p -= NT - I; I++; }
    int J = I + p;
    bool offd = (J > I);

    // ---- Load 4 tiles (h1[I], h2[I], h1[J], h2[J]) into swizzled SMEM
    {
        const uint4* base[4] = {
            (const uint4*)(g_h1q + (size_t)I * 128 * DDIM),
            (const uint4*)(g_h2q + (size_t)I * 128 * DDIM),
            (const uint4*)(g_h1q + (size_t)J * 128 * DDIM),
            (const uint4*)(g_h2q + (size_t)J * 128 * DDIM)
        };
        #pragma unroll
        for (int it = 0; it < 16; it++) {
            int tile = it >> 2;
            int lidx = tid + (it & 3) * 256;
            int r = lidx >> 3, c = lidx & 7;
            uint32_t off = (uint32_t)tile * SM_TILE + (uint32_t)r * 128u
                         + (uint32_t)((c ^ (r & 7)) << 4);
            *(uint4*)(smem + off) = base[tile][lidx];
        }
    }
    __syncthreads();

    int wm = wid >> 2;          // 0..1  (M)
    int wn = wid & 3;           // 0..3  (N)
    int a_r  = wm * 64 + (lane & 15);
    int a_cp = lane >> 4;
    int b_r  = wn * 32 + ((lane >> 4) << 3) + (lane & 7);
    int b_cp = (lane >> 3) & 1;

    int ngemm = offd ? 4 : 3;

    #pragma unroll 1
    for (int g = 0; g < ngemm; g++) {
        // A from I-side tiles {0:h1I,1:h2I}, B from J-side {2:h1J,3:h2J}
        uint32_t As = ((g == 1 || g == 3) ? 1u : 0u) * SM_TILE;
        uint32_t Bs = ((g == 1 || g == 2) ? 3u : 2u) * SM_TILE;

        float* Rrow; float* Rcol; bool docol;
        if (g == 0)      { Rrow = g_R + I*128;             Rcol = g_R + J*128;             docol = offd; }
        else if (g == 1) { Rrow = g_R + 3*NROWS + I*128;   Rcol = g_R + 3*NROWS + J*128;   docol = offd; }
        else if (g == 2) { Rrow = g_R + NROWS + I*128;     Rcol = g_R + 2*NROWS + J*128;   docol = true; }
        else             { Rrow = g_R + 2*NROWS + I*128;   Rcol = g_R + NROWS + J*128;     docol = true; }

        // ---- Preload ALL B fragments for this GEMM (8 LDSM, 32 regs)
        uint32_t b[4][4][2];   // [kstep][ntile][half]
        #pragma unroll
        for (int ks = 0; ks < 4; ks++) {
            int kc = ks * 2;
            #pragma unroll
            for (int np = 0; np < 2; np++) {
                int r = b_r + np * 16;
                uint32_t addr = sb + Bs + (uint32_t)r * 128u
                              + (uint32_t)(((kc + b_cp) ^ (r & 7)) << 4);
                ldsm_x4(b[ks][np*2][0], b[ks][np*2][1],
                        b[ks][np*2+1][0], b[ks][np*2+1][1], addr);
            }
        }

        float cp[4][2];
        #pragma unroll
        for (int nt = 0; nt < 4; nt++) { cp[nt][0] = 0.f; cp[nt][1] = 0.f; }

        // ---- 4 independent strips of 16 rows: MMA + fused epilogue
        #pragma unroll
        for (int mt = 0; mt < 4; mt++) {
            uint32_t a[4][4];
            int r = a_r + mt * 16;
            #pragma unroll
            for (int ks = 0; ks < 4; ks++) {
                uint32_t addr = sb + As + (uint32_t)r * 128u
                              + (uint32_t)(((ks * 2 + a_cp) ^ (r & 7)) << 4);
                ldsm_x4(a[ks][0], a[ks][1], a[ks][2], a[ks][3], addr);
            }

            float acc[4][4];
            #pragma unroll
            for (int nt = 0; nt < 4; nt++)
                #pragma unroll
                for (int v = 0; v < 4; v++) acc[nt][v] = 0.0f;

            #pragma unroll
            for (int ks = 0; ks < 4; ks++)
                #pragma unroll
                for (int nt = 0; nt < 4; nt++)
                    mma_fp8(acc[nt], a[ks], b[ks][nt]);

            // Strip epilogue: e = 2^acc (scale folded into quantization)
            float rp0 = 0.f, rp1 = 0.f;
            #pragma unroll
            for (int nt = 0; nt < 4; nt++) {
                float e0, e1, e2, e3;
                asm("ex2.approx.f32 %0, %1;" : "=f"(e0) : "f"(acc[nt][0]));
                asm("ex2.approx.f32 %0, %1;" : "=f"(e1) : "f"(acc[nt][1]));
                asm("ex2.approx.f32 %0, %1;" : "=f"(e2) : "f"(acc[nt][2]));
                asm("ex2.approx.f32 %0, %1;" : "=f"(e3) : "f"(acc[nt][3]));
                rp0 += e0 + e1;
                rp1 += e2 + e3;
                cp[nt][0] += e0 + e2;
                cp[nt][1] += e1 + e3;
            }
            rp0 += __shfl_xor_sync(0xffffffffu, rp0, 1);
            rp0 += __shfl_xor_sync(0xffffffffu, rp0, 2);
            rp1 += __shfl_xor_sync(0xffffffffu, rp1, 1);
            rp1 += __shfl_xor_sync(0xffffffffu, rp1, 2);
            if ((lane & 3) == 0) {
                int r0 = wm * 64 + mt * 16 + (lane >> 2);
                atomicAdd(&Rrow[r0],     rp0);
                atomicAdd(&Rrow[r0 + 8], rp1);
            }
        }

        // ---- Column sums for this GEMM
        if (docol) {
            #pragma unroll
            for (int nt = 0; nt < 4; nt++)
                #pragma unroll
                for (int h = 0; h < 2; h++) {
                    cp[nt][h] += __shfl_xor_sync(0xffffffffu, cp[nt][h], 4);
                    cp[nt][h] += __shfl_xor_sync(0xffffffffu, cp[nt][h], 8);
                    cp[nt][h] += __shfl_xor_sync(0xffffffffu, cp[nt][h], 16);
                }
            if (lane < 4) {
                int c0 = wn * 32 + lane * 2;
                #pragma unroll
                for (int nt = 0; nt < 4; nt++) {
                    atomicAdd(&Rcol[c0 + nt * 8],     cp[nt][0]);
                    atomicAdd(&Rcol[c0 + nt * 8 + 1], cp[nt][1]);
                }
            }
        }
    }
}

// ---------------------------------------------------------------------------
// Final scalar: 32 blocks x 256 threads, one row per thread.
// ---------------------------------------------------------------------------
__global__ void final_kernel(float* out) {
    __shared__ float sm[256];
    int t = threadIdx.x;
    int i = blockIdx.x * 256 + t;
    const float E5 = 148.4131591f;   // exp(1/tau), tau = 0.2

    float n1 = g_R[i]             + g_R[NROWS + i]     - E5;
    float n2 = g_R[3 * NROWS + i] + g_R[2 * NROWS + i] - E5;
    float s  = 0.5f * (logf(n1) + logf(n2)) - 5.0f * g_diag[i];

    sm[t] = s;
    __syncthreads();
    #pragma unroll
    for (int o = 128; o > 0; o >>= 1) {
        if (t < o) sm[t] += sm[t + o];
        __syncthreads();
    }
    if (t == 0) atomicAdd(out, sm[0] * (1.0f / NROWS));
}

// ---------------------------------------------------------------------------
extern "C" void kernel_launch(void* const* d_in, const int* in_sizes, int n_in,
                              void* d_out, int out_size) {
    const float* h1 = (const float*)d_in[0];
    const float* h2 = (const float*)d_in[1];
    float* out = (float*)d_out;

    cudaFuncSetAttribute(mma_exp_kernel,
                         cudaFuncAttributeMaxDynamicSharedMemorySize, SM_TOTAL);

    norm_kernel<<<(NROWS * 32) / 256, 256>>>(h1, h2, out);
    mma_exp_kernel<<<NPAIR, 256, SM_TOTAL>>>();
    final_kernel<<<NROWS / 256, 256>>>(out);
}